// round 4
// baseline (speedup 1.0000x reference)
#include <cuda_runtime.h>
#include <mma.h>

using namespace nvcuda;

#define NCLS   128
#define DIM    2048
#define NPTS   4096
#define CAP    512
#define KSPLIT 32
#define KCHUNK (DIM / KSPLIT)   // 64
#define PAIRS  (NCLS * NCLS)

// ---------------- scratch (device globals: no allocation allowed) ----------------
__device__ int    g_cnt[NCLS];
__device__ int    g_idx[NCLS * CAP];
__device__ float  g_meanR[NCLS * DIM];
__device__ float  g_meanT[NCLS * DIM];
__device__ float  g_meanC[NCLS * DIM];
__device__ float  g_nR[NCLS * 4];
__device__ float  g_nT[NCLS * 4];
__device__ float  g_nC[NCLS * 4];
__device__ float  g_S1p[KSPLIT * PAIRS];   // split-K partial dots meanR . meanC
__device__ float  g_S2p[KSPLIT * PAIRS];   // split-K partial dots meanT . meanC
__device__ double g_blk[NCLS];

// ---------------- kernel 1: zero counters ----------------
__global__ void k_zero() {
    int t = threadIdx.x;
    if (t < NCLS) g_cnt[t] = 0;
}

// ---------------- kernel 2: scatter row indices by class ----------------
__global__ void k_scatter(const int* __restrict__ tg) {
    int i = blockIdx.x * blockDim.x + threadIdx.x;
    if (i < NPTS) {
        int t = tg[i];
        int p = atomicAdd(&g_cnt[t], 1);
        g_idx[t * CAP + p] = i;
    }
}

// ---------------- kernel 3: segment means + norms ----------------
// grid: 512 blocks = 128 classes x 4 column chunks; 128 threads; thread owns 1 float4
__global__ void k_means(const float* __restrict__ m1, const float* __restrict__ m2) {
    int c  = blockIdx.x >> 2;
    int ch = blockIdx.x & 3;
    int off = ch * 512 + threadIdx.x * 4;

    __shared__ int sidx[CAP];
    int n = g_cnt[c];
    for (int j = threadIdx.x; j < n; j += 128)
        sidx[j] = g_idx[c * CAP + j] * DIM;
    __syncthreads();

    float4 aR = make_float4(0.f, 0.f, 0.f, 0.f);
    float4 aT = make_float4(0.f, 0.f, 0.f, 0.f);

    int j = 0;
    for (; j + 4 <= n; j += 4) {
        int i0 = sidx[j], i1 = sidx[j + 1], i2 = sidx[j + 2], i3 = sidx[j + 3];
        float4 r0 = *(const float4*)(m1 + i0 + off);
        float4 r1 = *(const float4*)(m1 + i1 + off);
        float4 r2 = *(const float4*)(m1 + i2 + off);
        float4 r3 = *(const float4*)(m1 + i3 + off);
        float4 t0 = *(const float4*)(m2 + i0 + off);
        float4 t1 = *(const float4*)(m2 + i1 + off);
        float4 t2 = *(const float4*)(m2 + i2 + off);
        float4 t3 = *(const float4*)(m2 + i3 + off);
        aR.x += (r0.x + r1.x) + (r2.x + r3.x);
        aR.y += (r0.y + r1.y) + (r2.y + r3.y);
        aR.z += (r0.z + r1.z) + (r2.z + r3.z);
        aR.w += (r0.w + r1.w) + (r2.w + r3.w);
        aT.x += (t0.x + t1.x) + (t2.x + t3.x);
        aT.y += (t0.y + t1.y) + (t2.y + t3.y);
        aT.z += (t0.z + t1.z) + (t2.z + t3.z);
        aT.w += (t0.w + t1.w) + (t2.w + t3.w);
    }
    for (; j < n; j++) {
        int i0 = sidx[j];
        float4 r0 = *(const float4*)(m1 + i0 + off);
        float4 t0 = *(const float4*)(m2 + i0 + off);
        aR.x += r0.x; aR.y += r0.y; aR.z += r0.z; aR.w += r0.w;
        aT.x += t0.x; aT.y += t0.y; aT.z += t0.z; aT.w += t0.w;
    }

    float inv = 1.f / (float)max(n, 1);
    float4 mR = make_float4(aR.x * inv, aR.y * inv, aR.z * inv, aR.w * inv);
    float4 mT = make_float4(aT.x * inv, aT.y * inv, aT.z * inv, aT.w * inv);
    float4 mC = make_float4(0.5f * (mR.x + mT.x), 0.5f * (mR.y + mT.y),
                            0.5f * (mR.z + mT.z), 0.5f * (mR.w + mT.w));

    int wb = c * DIM + off;
    *(float4*)(g_meanR + wb) = mR;
    *(float4*)(g_meanT + wb) = mT;
    *(float4*)(g_meanC + wb) = mC;

    float sR = mR.x*mR.x + mR.y*mR.y + mR.z*mR.z + mR.w*mR.w;
    float sT = mT.x*mT.x + mT.y*mT.y + mT.z*mT.z + mT.w*mT.w;
    float sC = mC.x*mC.x + mC.y*mC.y + mC.z*mC.z + mC.w*mC.w;

    #pragma unroll
    for (int o = 16; o > 0; o >>= 1) {
        sR += __shfl_down_sync(0xffffffffu, sR, o);
        sT += __shfl_down_sync(0xffffffffu, sT, o);
        sC += __shfl_down_sync(0xffffffffu, sC, o);
    }
    __shared__ float shn[3][4];
    int warp = threadIdx.x >> 5, lane = threadIdx.x & 31;
    if (lane == 0) { shn[0][warp] = sR; shn[1][warp] = sT; shn[2][warp] = sC; }
    __syncthreads();
    if (threadIdx.x == 0) {
        g_nR[c * 4 + ch] = shn[0][0] + shn[0][1] + shn[0][2] + shn[0][3];
        g_nT[c * 4 + ch] = shn[1][0] + shn[1][1] + shn[1][2] + shn[1][3];
        g_nC[c * 4 + ch] = shn[2][0] + shn[2][1] + shn[2][2] + shn[2][3];
    }
}

// ---------------- kernel 4: tf32 tensor-core split-K GEMMs ----------------
// grid: 256 blocks = 32 K-splits x 8; 8 warps/block; warp = one 16x16 output tile
// Fragments loaded directly from L2-resident mean matrices (no smem, no syncs).
__global__ void k_gemm_tc() {
    int split   = blockIdx.x >> 3;          // 0..31
    int blkTile = blockIdx.x & 7;           // 0..7
    int w       = threadIdx.x >> 5;         // 0..7
    int tileId  = blkTile * 8 + w;          // 0..63
    int aRow    = (tileId >> 3) * 16;       // 0..112
    int bCol    = (tileId & 7) * 16;        // 0..112
    int k0      = split * KCHUNK;

    wmma::fragment<wmma::accumulator, 16, 16, 8, float> acc1, acc2;
    wmma::fill_fragment(acc1, 0.0f);
    wmma::fill_fragment(acc2, 0.0f);

    #pragma unroll
    for (int k = 0; k < KCHUNK; k += 8) {
        wmma::fragment<wmma::matrix_a, 16, 16, 8, wmma::precision::tf32, wmma::row_major> fR, fT;
        wmma::fragment<wmma::matrix_b, 16, 16, 8, wmma::precision::tf32, wmma::col_major> fC;

        wmma::load_matrix_sync(fR, g_meanR + aRow * DIM + k0 + k, DIM);
        wmma::load_matrix_sync(fT, g_meanT + aRow * DIM + k0 + k, DIM);
        wmma::load_matrix_sync(fC, g_meanC + bCol * DIM + k0 + k, DIM);

        #pragma unroll
        for (int i = 0; i < fR.num_elements; i++) fR.x[i] = wmma::__float_to_tf32(fR.x[i]);
        #pragma unroll
        for (int i = 0; i < fT.num_elements; i++) fT.x[i] = wmma::__float_to_tf32(fT.x[i]);
        #pragma unroll
        for (int i = 0; i < fC.num_elements; i++) fC.x[i] = wmma::__float_to_tf32(fC.x[i]);

        wmma::mma_sync(acc1, fR, fC, acc1);
        wmma::mma_sync(acc2, fT, fC, acc2);
    }

    wmma::store_matrix_sync(g_S1p + split * PAIRS + aRow * NCLS + bCol, acc1, NCLS, wmma::mem_row_major);
    wmma::store_matrix_sync(g_S2p + split * PAIRS + aRow * NCLS + bCol, acc2, NCLS, wmma::mem_row_major);
}

// ---------------- kernel 5: per-pair loss + block reduce ----------------
__global__ void k_pair() {
    int a = blockIdx.x, b = threadIdx.x;

    float dot1 = 0.f, dot2 = 0.f;
    #pragma unroll
    for (int s = 0; s < KSPLIT; s++) {
        dot1 += g_S1p[s * PAIRS + a * NCLS + b];
        dot2 += g_S2p[s * PAIRS + a * NCLS + b];
    }
    float nRa = g_nR[a*4+0] + g_nR[a*4+1] + g_nR[a*4+2] + g_nR[a*4+3];
    float nTa = g_nT[a*4+0] + g_nT[a*4+1] + g_nT[a*4+2] + g_nT[a*4+3];
    float nCb = g_nC[b*4+0] + g_nC[b*4+1] + g_nC[b*4+2] + g_nC[b*4+3];

    float sq1 = fmaxf(nRa + nCb - 2.f * dot1, 1e-12f);
    float d1  = sqrtf(sq1);
    float dd1 = sqrtf(d1 + 1e-10f);
    float h1  = fmaxf(0.5f - dd1, 0.f);
    float t1  = (a == b) ? sq1 : h1 * h1;

    float sq2 = fmaxf(nTa + nCb - 2.f * dot2, 1e-12f);
    float d2  = sqrtf(sq2);
    float dd2 = sqrtf(d2 + 1e-10f);
    float h2  = fmaxf(0.5f - dd2, 0.f);
    float t2  = (a == b) ? sq2 : h2 * h2;

    double w = (double)g_cnt[a] * (double)g_cnt[b];
    double v = w * ((double)t1 + (double)t2);

    #pragma unroll
    for (int o = 16; o > 0; o >>= 1)
        v += __shfl_down_sync(0xffffffffu, v, o);
    __shared__ double shd[4];
    int warp = threadIdx.x >> 5, lane = threadIdx.x & 31;
    if (lane == 0) shd[warp] = v;
    __syncthreads();
    if (threadIdx.x == 0)
        g_blk[a] = shd[0] + shd[1] + shd[2] + shd[3];
}

// ---------------- kernel 6: final scalar ----------------
__global__ void k_final(float* __restrict__ out, int out_n) {
    double v = g_blk[threadIdx.x];
    #pragma unroll
    for (int o = 16; o > 0; o >>= 1)
        v += __shfl_down_sync(0xffffffffu, v, o);
    __shared__ double shd[4];
    __shared__ double total;
    int warp = threadIdx.x >> 5, lane = threadIdx.x & 31;
    if (lane == 0) shd[warp] = v;
    __syncthreads();
    if (threadIdx.x == 0)
        total = (shd[0] + shd[1] + shd[2] + shd[3]) / (4096.0 * 4096.0);
    __syncthreads();
    float r = (float)total;
    for (int i = threadIdx.x; i < out_n; i += blockDim.x) out[i] = r;
}

extern "C" void kernel_launch(void* const* d_in, const int* in_sizes, int n_in,
                              void* d_out, int out_size) {
    const float* m1 = (const float*)d_in[0];
    const float* m2 = (const float*)d_in[1];
    const int*   tg = (const int*)d_in[2];
    float* out = (float*)d_out;

    k_zero<<<1, 128>>>();
    k_scatter<<<16, 256>>>(tg);
    k_means<<<NCLS * 4, 128>>>(m1, m2);
    k_gemm_tc<<<KSPLIT * 8, 256>>>();
    k_pair<<<NCLS, NCLS>>>();
    k_final<<<1, 128>>>(out, out_size);
}

// round 5
// speedup vs baseline: 1.5829x; 1.5829x over previous
#include <cuda_runtime.h>
#include <mma.h>

using namespace nvcuda;

#define NCLS   128
#define DIM    2048
#define NPTS   4096
#define CAP    512
#define KSPLIT 64
#define KCHUNK (DIM / KSPLIT)   // 32
#define PAIRS  (NCLS * NCLS)
#define LDP    40               // padded smem stride (floats), mult of 8

// ---------------- scratch (device globals: no allocation allowed) ----------------
__device__ int    g_cnt[NCLS];            // zero-initialized; k_final re-zeroes each run
__device__ int    g_idx[NCLS * CAP];
__device__ float  g_meanR[NCLS * DIM];
__device__ float  g_meanT[NCLS * DIM];
__device__ float  g_meanC[NCLS * DIM];
__device__ float  g_nR[NCLS * 4];
__device__ float  g_nT[NCLS * 4];
__device__ float  g_nC[NCLS * 4];
__device__ float  g_S1p[KSPLIT * PAIRS];  // split-K partial dots meanR . meanC
__device__ float  g_S2p[KSPLIT * PAIRS];  // split-K partial dots meanT . meanC
__device__ double g_blk[NCLS];
__device__ int    g_cntc[NCLS];           // stable copy of counts for k_pair

// ---------------- kernel 1: scatter row indices by class ----------------
__global__ void k_scatter(const int* __restrict__ tg) {
    int i = blockIdx.x * blockDim.x + threadIdx.x;
    if (i < NPTS) {
        int t = tg[i];
        int p = atomicAdd(&g_cnt[t], 1);
        g_idx[t * CAP + p] = i;
    }
}

// ---------------- kernel 2: segment means + norms ----------------
// grid: 512 blocks = 128 classes x 4 column chunks; 128 threads; thread owns 1 float4
__global__ void k_means(const float* __restrict__ m1, const float* __restrict__ m2) {
    int c  = blockIdx.x >> 2;
    int ch = blockIdx.x & 3;
    int off = ch * 512 + threadIdx.x * 4;

    __shared__ int sidx[CAP];
    int n = g_cnt[c];
    for (int j = threadIdx.x; j < n; j += 128)
        sidx[j] = g_idx[c * CAP + j] * DIM;
    __syncthreads();

    float4 aR = make_float4(0.f, 0.f, 0.f, 0.f);
    float4 aT = make_float4(0.f, 0.f, 0.f, 0.f);

    int j = 0;
    for (; j + 4 <= n; j += 4) {
        int i0 = sidx[j], i1 = sidx[j + 1], i2 = sidx[j + 2], i3 = sidx[j + 3];
        float4 r0 = *(const float4*)(m1 + i0 + off);
        float4 r1 = *(const float4*)(m1 + i1 + off);
        float4 r2 = *(const float4*)(m1 + i2 + off);
        float4 r3 = *(const float4*)(m1 + i3 + off);
        float4 t0 = *(const float4*)(m2 + i0 + off);
        float4 t1 = *(const float4*)(m2 + i1 + off);
        float4 t2 = *(const float4*)(m2 + i2 + off);
        float4 t3 = *(const float4*)(m2 + i3 + off);
        aR.x += (r0.x + r1.x) + (r2.x + r3.x);
        aR.y += (r0.y + r1.y) + (r2.y + r3.y);
        aR.z += (r0.z + r1.z) + (r2.z + r3.z);
        aR.w += (r0.w + r1.w) + (r2.w + r3.w);
        aT.x += (t0.x + t1.x) + (t2.x + t3.x);
        aT.y += (t0.y + t1.y) + (t2.y + t3.y);
        aT.z += (t0.z + t1.z) + (t2.z + t3.z);
        aT.w += (t0.w + t1.w) + (t2.w + t3.w);
    }
    for (; j < n; j++) {
        int i0 = sidx[j];
        float4 r0 = *(const float4*)(m1 + i0 + off);
        float4 t0 = *(const float4*)(m2 + i0 + off);
        aR.x += r0.x; aR.y += r0.y; aR.z += r0.z; aR.w += r0.w;
        aT.x += t0.x; aT.y += t0.y; aT.z += t0.z; aT.w += t0.w;
    }

    float inv = 1.f / (float)max(n, 1);
    float4 mR = make_float4(aR.x * inv, aR.y * inv, aR.z * inv, aR.w * inv);
    float4 mT = make_float4(aT.x * inv, aT.y * inv, aT.z * inv, aT.w * inv);
    float4 mC = make_float4(0.5f * (mR.x + mT.x), 0.5f * (mR.y + mT.y),
                            0.5f * (mR.z + mT.z), 0.5f * (mR.w + mT.w));

    int wb = c * DIM + off;
    *(float4*)(g_meanR + wb) = mR;
    *(float4*)(g_meanT + wb) = mT;
    *(float4*)(g_meanC + wb) = mC;

    float sR = mR.x*mR.x + mR.y*mR.y + mR.z*mR.z + mR.w*mR.w;
    float sT = mT.x*mT.x + mT.y*mT.y + mT.z*mT.z + mT.w*mT.w;
    float sC = mC.x*mC.x + mC.y*mC.y + mC.z*mC.z + mC.w*mC.w;

    #pragma unroll
    for (int o = 16; o > 0; o >>= 1) {
        sR += __shfl_down_sync(0xffffffffu, sR, o);
        sT += __shfl_down_sync(0xffffffffu, sT, o);
        sC += __shfl_down_sync(0xffffffffu, sC, o);
    }
    __shared__ float shn[3][4];
    int warp = threadIdx.x >> 5, lane = threadIdx.x & 31;
    if (lane == 0) { shn[0][warp] = sR; shn[1][warp] = sT; shn[2][warp] = sC; }
    __syncthreads();
    if (threadIdx.x == 0) {
        g_nR[c * 4 + ch] = shn[0][0] + shn[0][1] + shn[0][2] + shn[0][3];
        g_nT[c * 4 + ch] = shn[1][0] + shn[1][1] + shn[1][2] + shn[1][3];
        g_nC[c * 4 + ch] = shn[2][0] + shn[2][1] + shn[2][2] + shn[2][3];
        if (ch == 0) g_cntc[c] = n;
    }
}

// ---------------- kernel 3: tf32 tensor-core split-K GEMMs (smem-staged) ----------------
// grid: 256 blocks = 64 K-splits x (2x2 tiles of 64x64); 256 threads (8 warps)
// Load phase: coalesced float4 global->smem (padded stride), then 4 k-steps of mma.
__global__ void k_gemm_tc() {
    __shared__ float Rs[64 * LDP];
    __shared__ float Ts[64 * LDP];
    __shared__ float Cs[64 * LDP];

    int ks    = blockIdx.x >> 2;
    int tile  = blockIdx.x & 3;
    int aBase = (tile >> 1) * 64;
    int bBase = (tile & 1) * 64;
    int k0    = ks * KCHUNK;
    int tid   = threadIdx.x;

    // each array: 64 rows x 8 float4 = 512 float4; 256 threads -> 2 each
    #pragma unroll
    for (int i = tid; i < 512; i += 256) {
        int row = i >> 3;
        int c4  = (i & 7) * 4;
        *(float4*)&Rs[row * LDP + c4] = *(const float4*)(g_meanR + (aBase + row) * DIM + k0 + c4);
        *(float4*)&Ts[row * LDP + c4] = *(const float4*)(g_meanT + (aBase + row) * DIM + k0 + c4);
        *(float4*)&Cs[row * LDP + c4] = *(const float4*)(g_meanC + (bBase + row) * DIM + k0 + c4);
    }
    __syncthreads();

    int w  = tid >> 5;
    int wm = (w & 3) * 16;        // m offset within 64
    int wn = (w >> 2) * 32;       // n offset within 64 (0 or 32); warp does n=wn, wn+16

    wmma::fragment<wmma::accumulator, 16, 16, 8, float> acc1[2], acc2[2];
    wmma::fill_fragment(acc1[0], 0.0f); wmma::fill_fragment(acc1[1], 0.0f);
    wmma::fill_fragment(acc2[0], 0.0f); wmma::fill_fragment(acc2[1], 0.0f);

    #pragma unroll
    for (int k = 0; k < KCHUNK; k += 8) {
        wmma::fragment<wmma::matrix_a, 16, 16, 8, wmma::precision::tf32, wmma::row_major> fR, fT;
        wmma::fragment<wmma::matrix_b, 16, 16, 8, wmma::precision::tf32, wmma::col_major> fC0, fC1;

        wmma::load_matrix_sync(fR,  Rs + wm * LDP + k, LDP);
        wmma::load_matrix_sync(fT,  Ts + wm * LDP + k, LDP);
        wmma::load_matrix_sync(fC0, Cs + wn * LDP + k, LDP);
        wmma::load_matrix_sync(fC1, Cs + (wn + 16) * LDP + k, LDP);

        #pragma unroll
        for (int i = 0; i < fR.num_elements; i++)  fR.x[i]  = wmma::__float_to_tf32(fR.x[i]);
        #pragma unroll
        for (int i = 0; i < fT.num_elements; i++)  fT.x[i]  = wmma::__float_to_tf32(fT.x[i]);
        #pragma unroll
        for (int i = 0; i < fC0.num_elements; i++) fC0.x[i] = wmma::__float_to_tf32(fC0.x[i]);
        #pragma unroll
        for (int i = 0; i < fC1.num_elements; i++) fC1.x[i] = wmma::__float_to_tf32(fC1.x[i]);

        wmma::mma_sync(acc1[0], fR, fC0, acc1[0]);
        wmma::mma_sync(acc1[1], fR, fC1, acc1[1]);
        wmma::mma_sync(acc2[0], fT, fC0, acc2[0]);
        wmma::mma_sync(acc2[1], fT, fC1, acc2[1]);
    }

    float* o1 = g_S1p + ks * PAIRS + (aBase + wm) * NCLS + bBase + wn;
    float* o2 = g_S2p + ks * PAIRS + (aBase + wm) * NCLS + bBase + wn;
    wmma::store_matrix_sync(o1,      acc1[0], NCLS, wmma::mem_row_major);
    wmma::store_matrix_sync(o1 + 16, acc1[1], NCLS, wmma::mem_row_major);
    wmma::store_matrix_sync(o2,      acc2[0], NCLS, wmma::mem_row_major);
    wmma::store_matrix_sync(o2 + 16, acc2[1], NCLS, wmma::mem_row_major);
}

// ---------------- kernel 4: per-pair loss + block reduce ----------------
__global__ void k_pair() {
    int a = blockIdx.x, b = threadIdx.x;

    float dot1 = 0.f, dot2 = 0.f;
    #pragma unroll
    for (int s = 0; s < KSPLIT; s++) {
        dot1 += g_S1p[s * PAIRS + a * NCLS + b];
        dot2 += g_S2p[s * PAIRS + a * NCLS + b];
    }
    float nRa = g_nR[a*4+0] + g_nR[a*4+1] + g_nR[a*4+2] + g_nR[a*4+3];
    float nTa = g_nT[a*4+0] + g_nT[a*4+1] + g_nT[a*4+2] + g_nT[a*4+3];
    float nCb = g_nC[b*4+0] + g_nC[b*4+1] + g_nC[b*4+2] + g_nC[b*4+3];

    float sq1 = fmaxf(nRa + nCb - 2.f * dot1, 1e-12f);
    float d1  = sqrtf(sq1);
    float dd1 = sqrtf(d1 + 1e-10f);
    float h1  = fmaxf(0.5f - dd1, 0.f);
    float t1  = (a == b) ? sq1 : h1 * h1;

    float sq2 = fmaxf(nTa + nCb - 2.f * dot2, 1e-12f);
    float d2  = sqrtf(sq2);
    float dd2 = sqrtf(d2 + 1e-10f);
    float h2  = fmaxf(0.5f - dd2, 0.f);
    float t2  = (a == b) ? sq2 : h2 * h2;

    double w = (double)g_cntc[a] * (double)g_cntc[b];
    double v = w * ((double)t1 + (double)t2);

    #pragma unroll
    for (int o = 16; o > 0; o >>= 1)
        v += __shfl_down_sync(0xffffffffu, v, o);
    __shared__ double shd[4];
    int warp = threadIdx.x >> 5, lane = threadIdx.x & 31;
    if (lane == 0) shd[warp] = v;
    __syncthreads();
    if (threadIdx.x == 0)
        g_blk[a] = shd[0] + shd[1] + shd[2] + shd[3];
}

// ---------------- kernel 5: final scalar (+ re-zero counters for next run) ----------------
__global__ void k_final(float* __restrict__ out, int out_n) {
    double v = g_blk[threadIdx.x];
    #pragma unroll
    for (int o = 16; o > 0; o >>= 1)
        v += __shfl_down_sync(0xffffffffu, v, o);
    __shared__ double shd[4];
    __shared__ double total;
    int warp = threadIdx.x >> 5, lane = threadIdx.x & 31;
    if (lane == 0) shd[warp] = v;
    __syncthreads();
    if (threadIdx.x == 0)
        total = (shd[0] + shd[1] + shd[2] + shd[3]) / (4096.0 * 4096.0);
    __syncthreads();
    float r = (float)total;
    for (int i = threadIdx.x; i < out_n; i += blockDim.x) out[i] = r;
    g_cnt[threadIdx.x] = 0;   // leave counters zeroed for the next launch
}

extern "C" void kernel_launch(void* const* d_in, const int* in_sizes, int n_in,
                              void* d_out, int out_size) {
    const float* m1 = (const float*)d_in[0];
    const float* m2 = (const float*)d_in[1];
    const int*   tg = (const int*)d_in[2];
    float* out = (float*)d_out;

    k_scatter<<<16, 256>>>(tg);
    k_means<<<NCLS * 4, 128>>>(m1, m2);
    k_gemm_tc<<<KSPLIT * 4, 256>>>();
    k_pair<<<NCLS, NCLS>>>();
    k_final<<<1, 128>>>(out, out_size);
}

// round 6
// speedup vs baseline: 1.5849x; 1.0013x over previous
#include <cuda_runtime.h>
#include <mma.h>

using namespace nvcuda;

#define NCLS   128
#define DIM    2048
#define NPTS   4096
#define CAP    512
#define KSPLIT 64
#define KCHUNK (DIM / KSPLIT)   // 32
#define PAIRS  (NCLS * NCLS)
#define LDP    40               // padded smem stride (floats), mult of 8

// ---------------- scratch (device globals: no allocation allowed) ----------------
__device__ int    g_cnt[NCLS];            // zero-initialized; k_final re-zeroes each run
__device__ int    g_idx[NCLS * CAP];
__device__ float  g_meanR[NCLS * DIM];
__device__ float  g_meanT[NCLS * DIM];
__device__ float  g_meanC[NCLS * DIM];
__device__ float  g_nR[NCLS * 4];
__device__ float  g_nT[NCLS * 4];
__device__ float  g_nC[NCLS * 4];
__device__ float  g_S1p[KSPLIT * PAIRS];  // split-K partial dots meanR . meanC
__device__ float  g_S2p[KSPLIT * PAIRS];  // split-K partial dots meanT . meanC
__device__ float  g_Sh[4 * PAIRS];        // half-reduced dots: [mat*2+half][pair]
__device__ double g_blk[NCLS];
__device__ int    g_cntc[NCLS];           // stable copy of counts for k_pair

// ---------------- kernel 1: scatter row indices by class ----------------
__global__ void k_scatter(const int* __restrict__ tg) {
    int i = blockIdx.x * blockDim.x + threadIdx.x;
    if (i < NPTS) {
        int t = tg[i];
        int p = atomicAdd(&g_cnt[t], 1);
        g_idx[t * CAP + p] = i;
    }
}

// ---------------- kernel 2: segment means + norms ----------------
// grid: 512 blocks = 128 classes x 4 column chunks; 128 threads; thread owns 1 float4
__global__ void k_means(const float* __restrict__ m1, const float* __restrict__ m2) {
    int c  = blockIdx.x >> 2;
    int ch = blockIdx.x & 3;
    int off = ch * 512 + threadIdx.x * 4;

    __shared__ int sidx[CAP];
    int n = g_cnt[c];
    for (int j = threadIdx.x; j < n; j += 128)
        sidx[j] = g_idx[c * CAP + j] * DIM;
    __syncthreads();

    float4 aR = make_float4(0.f, 0.f, 0.f, 0.f);
    float4 aT = make_float4(0.f, 0.f, 0.f, 0.f);

    int j = 0;
    for (; j + 4 <= n; j += 4) {
        int i0 = sidx[j], i1 = sidx[j + 1], i2 = sidx[j + 2], i3 = sidx[j + 3];
        float4 r0 = *(const float4*)(m1 + i0 + off);
        float4 r1 = *(const float4*)(m1 + i1 + off);
        float4 r2 = *(const float4*)(m1 + i2 + off);
        float4 r3 = *(const float4*)(m1 + i3 + off);
        float4 t0 = *(const float4*)(m2 + i0 + off);
        float4 t1 = *(const float4*)(m2 + i1 + off);
        float4 t2 = *(const float4*)(m2 + i2 + off);
        float4 t3 = *(const float4*)(m2 + i3 + off);
        aR.x += (r0.x + r1.x) + (r2.x + r3.x);
        aR.y += (r0.y + r1.y) + (r2.y + r3.y);
        aR.z += (r0.z + r1.z) + (r2.z + r3.z);
        aR.w += (r0.w + r1.w) + (r2.w + r3.w);
        aT.x += (t0.x + t1.x) + (t2.x + t3.x);
        aT.y += (t0.y + t1.y) + (t2.y + t3.y);
        aT.z += (t0.z + t1.z) + (t2.z + t3.z);
        aT.w += (t0.w + t1.w) + (t2.w + t3.w);
    }
    for (; j < n; j++) {
        int i0 = sidx[j];
        float4 r0 = *(const float4*)(m1 + i0 + off);
        float4 t0 = *(const float4*)(m2 + i0 + off);
        aR.x += r0.x; aR.y += r0.y; aR.z += r0.z; aR.w += r0.w;
        aT.x += t0.x; aT.y += t0.y; aT.z += t0.z; aT.w += t0.w;
    }

    float inv = 1.f / (float)max(n, 1);
    float4 mR = make_float4(aR.x * inv, aR.y * inv, aR.z * inv, aR.w * inv);
    float4 mT = make_float4(aT.x * inv, aT.y * inv, aT.z * inv, aT.w * inv);
    float4 mC = make_float4(0.5f * (mR.x + mT.x), 0.5f * (mR.y + mT.y),
                            0.5f * (mR.z + mT.z), 0.5f * (mR.w + mT.w));

    int wb = c * DIM + off;
    *(float4*)(g_meanR + wb) = mR;
    *(float4*)(g_meanT + wb) = mT;
    *(float4*)(g_meanC + wb) = mC;

    float sR = mR.x*mR.x + mR.y*mR.y + mR.z*mR.z + mR.w*mR.w;
    float sT = mT.x*mT.x + mT.y*mT.y + mT.z*mT.z + mT.w*mT.w;
    float sC = mC.x*mC.x + mC.y*mC.y + mC.z*mC.z + mC.w*mC.w;

    #pragma unroll
    for (int o = 16; o > 0; o >>= 1) {
        sR += __shfl_down_sync(0xffffffffu, sR, o);
        sT += __shfl_down_sync(0xffffffffu, sT, o);
        sC += __shfl_down_sync(0xffffffffu, sC, o);
    }
    __shared__ float shn[3][4];
    int warp = threadIdx.x >> 5, lane = threadIdx.x & 31;
    if (lane == 0) { shn[0][warp] = sR; shn[1][warp] = sT; shn[2][warp] = sC; }
    __syncthreads();
    if (threadIdx.x == 0) {
        g_nR[c * 4 + ch] = shn[0][0] + shn[0][1] + shn[0][2] + shn[0][3];
        g_nT[c * 4 + ch] = shn[1][0] + shn[1][1] + shn[1][2] + shn[1][3];
        g_nC[c * 4 + ch] = shn[2][0] + shn[2][1] + shn[2][2] + shn[2][3];
        if (ch == 0) g_cntc[c] = n;
    }
}

// ---------------- kernel 3: tf32 tensor-core split-K GEMMs (smem-staged) ----------------
// grid: 256 blocks = 64 K-splits x (2x2 tiles of 64x64); 256 threads (8 warps)
__global__ void k_gemm_tc() {
    __shared__ float Rs[64 * LDP];
    __shared__ float Ts[64 * LDP];
    __shared__ float Cs[64 * LDP];

    int ks    = blockIdx.x >> 2;
    int tile  = blockIdx.x & 3;
    int aBase = (tile >> 1) * 64;
    int bBase = (tile & 1) * 64;
    int k0    = ks * KCHUNK;
    int tid   = threadIdx.x;

    #pragma unroll
    for (int i = tid; i < 512; i += 256) {
        int row = i >> 3;
        int c4  = (i & 7) * 4;
        *(float4*)&Rs[row * LDP + c4] = *(const float4*)(g_meanR + (aBase + row) * DIM + k0 + c4);
        *(float4*)&Ts[row * LDP + c4] = *(const float4*)(g_meanT + (aBase + row) * DIM + k0 + c4);
        *(float4*)&Cs[row * LDP + c4] = *(const float4*)(g_meanC + (bBase + row) * DIM + k0 + c4);
    }
    __syncthreads();

    int w  = tid >> 5;
    int wm = (w & 3) * 16;
    int wn = (w >> 2) * 32;

    wmma::fragment<wmma::accumulator, 16, 16, 8, float> acc1[2], acc2[2];
    wmma::fill_fragment(acc1[0], 0.0f); wmma::fill_fragment(acc1[1], 0.0f);
    wmma::fill_fragment(acc2[0], 0.0f); wmma::fill_fragment(acc2[1], 0.0f);

    #pragma unroll
    for (int k = 0; k < KCHUNK; k += 8) {
        wmma::fragment<wmma::matrix_a, 16, 16, 8, wmma::precision::tf32, wmma::row_major> fR, fT;
        wmma::fragment<wmma::matrix_b, 16, 16, 8, wmma::precision::tf32, wmma::col_major> fC0, fC1;

        wmma::load_matrix_sync(fR,  Rs + wm * LDP + k, LDP);
        wmma::load_matrix_sync(fT,  Ts + wm * LDP + k, LDP);
        wmma::load_matrix_sync(fC0, Cs + wn * LDP + k, LDP);
        wmma::load_matrix_sync(fC1, Cs + (wn + 16) * LDP + k, LDP);

        #pragma unroll
        for (int i = 0; i < fR.num_elements; i++)  fR.x[i]  = wmma::__float_to_tf32(fR.x[i]);
        #pragma unroll
        for (int i = 0; i < fT.num_elements; i++)  fT.x[i]  = wmma::__float_to_tf32(fT.x[i]);
        #pragma unroll
        for (int i = 0; i < fC0.num_elements; i++) fC0.x[i] = wmma::__float_to_tf32(fC0.x[i]);
        #pragma unroll
        for (int i = 0; i < fC1.num_elements; i++) fC1.x[i] = wmma::__float_to_tf32(fC1.x[i]);

        wmma::mma_sync(acc1[0], fR, fC0, acc1[0]);
        wmma::mma_sync(acc1[1], fR, fC1, acc1[1]);
        wmma::mma_sync(acc2[0], fT, fC0, acc2[0]);
        wmma::mma_sync(acc2[1], fT, fC1, acc2[1]);
    }

    float* o1 = g_S1p + ks * PAIRS + (aBase + wm) * NCLS + bBase + wn;
    float* o2 = g_S2p + ks * PAIRS + (aBase + wm) * NCLS + bBase + wn;
    wmma::store_matrix_sync(o1,      acc1[0], NCLS, wmma::mem_row_major);
    wmma::store_matrix_sync(o1 + 16, acc1[1], NCLS, wmma::mem_row_major);
    wmma::store_matrix_sync(o2,      acc2[0], NCLS, wmma::mem_row_major);
    wmma::store_matrix_sync(o2 + 16, acc2[1], NCLS, wmma::mem_row_major);
}

// ---------------- kernel 4: high-parallelism split reduction ----------------
// 65536 threads; one per (matrix, half, pair). Each sums 32 splits (coalesced, MLP=32).
__global__ void k_red() {
    int idx = blockIdx.x * blockDim.x + threadIdx.x;   // 0..65535
    int mat = idx >> 15;            // 0..1
    int rem = idx & 32767;
    int h   = rem >> 14;            // 0..1
    int p   = rem & 16383;          // pair

    const float* src = (mat ? g_S2p : g_S1p) + h * 32 * PAIRS + p;
    float s = 0.f;
    #pragma unroll
    for (int k = 0; k < 32; k++)
        s += src[k * PAIRS];
    g_Sh[((mat << 1) + h) * PAIRS + p] = s;
}

// ---------------- kernel 5: per-pair loss + block reduce ----------------
__global__ void k_pair() {
    int a = blockIdx.x, b = threadIdx.x;
    int p = a * NCLS + b;

    float dot1 = g_Sh[p] + g_Sh[PAIRS + p];
    float dot2 = g_Sh[2 * PAIRS + p] + g_Sh[3 * PAIRS + p];

    float nRa = g_nR[a*4+0] + g_nR[a*4+1] + g_nR[a*4+2] + g_nR[a*4+3];
    float nTa = g_nT[a*4+0] + g_nT[a*4+1] + g_nT[a*4+2] + g_nT[a*4+3];
    float nCb = g_nC[b*4+0] + g_nC[b*4+1] + g_nC[b*4+2] + g_nC[b*4+3];

    float sq1 = fmaxf(nRa + nCb - 2.f * dot1, 1e-12f);
    float d1  = sqrtf(sq1);
    float dd1 = sqrtf(d1 + 1e-10f);
    float h1  = fmaxf(0.5f - dd1, 0.f);
    float t1  = (a == b) ? sq1 : h1 * h1;

    float sq2 = fmaxf(nTa + nCb - 2.f * dot2, 1e-12f);
    float d2  = sqrtf(sq2);
    float dd2 = sqrtf(d2 + 1e-10f);
    float h2  = fmaxf(0.5f - dd2, 0.f);
    float t2  = (a == b) ? sq2 : h2 * h2;

    double w = (double)g_cntc[a] * (double)g_cntc[b];
    double v = w * ((double)t1 + (double)t2);

    #pragma unroll
    for (int o = 16; o > 0; o >>= 1)
        v += __shfl_down_sync(0xffffffffu, v, o);
    __shared__ double shd[4];
    int warp = threadIdx.x >> 5, lane = threadIdx.x & 31;
    if (lane == 0) shd[warp] = v;
    __syncthreads();
    if (threadIdx.x == 0)
        g_blk[a] = shd[0] + shd[1] + shd[2] + shd[3];
}

// ---------------- kernel 6: final scalar (+ re-zero counters for next run) ----------------
__global__ void k_final(float* __restrict__ out, int out_n) {
    double v = g_blk[threadIdx.x];
    #pragma unroll
    for (int o = 16; o > 0; o >>= 1)
        v += __shfl_down_sync(0xffffffffu, v, o);
    __shared__ double shd[4];
    __shared__ double total;
    int warp = threadIdx.x >> 5, lane = threadIdx.x & 31;
    if (lane == 0) shd[warp] = v;
    __syncthreads();
    if (threadIdx.x == 0)
        total = (shd[0] + shd[1] + shd[2] + shd[3]) / (4096.0 * 4096.0);
    __syncthreads();
    float r = (float)total;
    for (int i = threadIdx.x; i < out_n; i += blockDim.x) out[i] = r;
    g_cnt[threadIdx.x] = 0;
}

extern "C" void kernel_launch(void* const* d_in, const int* in_sizes, int n_in,
                              void* d_out, int out_size) {
    const float* m1 = (const float*)d_in[0];
    const float* m2 = (const float*)d_in[1];
    const int*   tg = (const int*)d_in[2];
    float* out = (float*)d_out;

    k_scatter<<<16, 256>>>(tg);
    k_means<<<NCLS * 4, 128>>>(m1, m2);
    k_gemm_tc<<<KSPLIT * 4, 256>>>();
    k_red<<<256, 256>>>();
    k_pair<<<NCLS, NCLS>>>();
    k_final<<<1, 128>>>(out, out_size);
}